// round 16
// baseline (speedup 1.0000x reference)
#include <cuda_runtime.h>
#include <cstdint>
#include <math.h>
#include <float.h>

// Problem constants
#define BK  8
#define CK  32
#define KK  512
#define ROWS 16
#define TPB 512

// Scratch: raw D per (b,i,j); a = 0.99*Dmin per (b,i)
__device__ float g_D[BK * KK * KK];    // 8 MB
__device__ float g_a[BK * KK];         // 16 KB

// ---------------------------------------------------------------------------
// JAX threefry2x32, key = (0, 42).  Random123 Threefry-2x32-20.
// Adds (round + key injection) issued as IMAD via opaque `one` (fma pipe);
// rotations single SHF via __funnelshift_l; xors LOP3. 3 ops per round.
// ---------------------------------------------------------------------------
#define MAD(dst, addend) \
    asm("mad.lo.s32 %0, %1, %2, %0;" : "+r"(dst) : "r"(addend), "r"(one))
#define MADC(dst, cst) { uint32_t k_ = (cst); MAD(dst, k_); }
#define TF_R(r) { MAD(x0, x1); x1 = __funnelshift_l(x1, x1, (r)); x1 ^= x0; }

__device__ __forceinline__ uint32_t jax_bits(uint32_t e, uint32_t one) {
    uint32_t x0 = 0u, x1 = e;
    const uint32_t ks1 = 42u;
    const uint32_t ks2 = 0x1BD11BDAu ^ 42u;
    /* x0 += 0 */  MADC(x1, ks1);
    TF_R(13) TF_R(15) TF_R(26) TF_R(6)
    MADC(x0, ks1); MADC(x1, ks2 + 1u);
    TF_R(17) TF_R(29) TF_R(16) TF_R(24)
    MADC(x0, ks2); MADC(x1, 2u);
    TF_R(13) TF_R(15) TF_R(26) TF_R(6)
    /* x0 += 0 */  MADC(x1, ks1 + 3u);
    TF_R(17) TF_R(29) TF_R(16) TF_R(24)
    MADC(x0, ks1); MADC(x1, ks2 + 4u);
    TF_R(13) TF_R(15) TF_R(26) TF_R(6)
    MADC(x0, ks2); MADC(x1, 5u);
    return x0 ^ x1;
}

// jax.random.uniform bit->float, minval=1e-10, maxval=1.0 (f32).
// f in [0,1) so max(1e-10, f+1e-10) == f+1e-10 exactly.
__device__ __forceinline__ float jax_uniform(uint32_t bits) {
    float f = __uint_as_float((bits >> 9) | 0x3f800000u) - 1.0f;
    return f + 1e-10f;
}

// ---------------------------------------------------------------------------
// Kernel 1: distances + row minima  ->  g_D (raw), g_a (0.99*Dmin)
// 256 blocks (single wave at 2 CTA/SM), 16 rows per block.
// Triggers the dependent sample launch at CTA entry (max PDL overlap).
// ---------------------------------------------------------------------------
__global__ void __launch_bounds__(TPB, 2)
dist_kernel(const float* __restrict__ amp,
            const float* __restrict__ ph,
            const float* __restrict__ Amat,
            const float* __restrict__ wamp_p,
            const float* __restrict__ wph_p) {
    __shared__ float sQi[ROWS][CK];      // row vectors q_i
    __shared__ float sSi[ROWS];          // ||q_i||^2
    __shared__ float sD[ROWS][KK];       // D tile for min reduction (32 KB)

    // Let the dependent sample kernel start launching right away; its
    // cudaGridDependencySynchronize() provides the data-ready guarantee.
    cudaTriggerProgrammaticLaunchCompletion();

    const int b    = blockIdx.y;
    const int j    = threadIdx.x;
    const int wid  = j >> 5;
    const int lane = j & 31;
    const int i0   = blockIdx.x * ROWS;

    const float wa = wamp_p[0];
    const float wp = wph_p[0];

    const float* ab = amp + (size_t)b * CK * KK;
    const float* pb = ph  + (size_t)b * CK * KK;

    // Per-thread column cache q_j[c] and its sum of squares
    float qj[CK];
    float Sj = 0.0f;
#pragma unroll
    for (int c = 0; c < CK; c++) {
        float v = wa * ab[c * KK + j] + wp * pb[c * KK + j];
        qj[c] = v;
        Sj = fmaf(v, v, Sj);
    }

    // Each of the 16 warps loads its row vector (lane = channel) + row SSQ
    {
        const int i = i0 + wid;
        float v = wa * ab[lane * KK + i] + wp * pb[lane * KK + i];
        sQi[wid][lane] = v;
        float s = v * v;
#pragma unroll
        for (int o = 16; o; o >>= 1)
            s += __shfl_xor_sync(0xffffffffu, s, o);
        if (lane == 0) sSi[wid] = s;
    }

    const float dj   = Amat[(size_t)j * KK + j];
    const float djsq = dj * dj;
    __syncthreads();

    // Phase A: D = djsq * ||q_i - q_j||^2 + 1e-10 (expanded dot); store only.
#pragma unroll
    for (int r = 0; r < ROWS; r++) {
        float dot = 0.0f;
        const float2* q2 = (const float2*)sQi[r];
#pragma unroll
        for (int c2 = 0; c2 < CK / 2; c2++) {
            float2 qi = q2[c2];
            dot = fmaf(qi.x, qj[2 * c2], dot);
            dot = fmaf(qi.y, qj[2 * c2 + 1], dot);
        }
        float ss = fmaxf(fmaf(dot, -2.0f, sSi[r] + Sj), 0.0f);
        const int i = i0 + r;
        float D = (i == j) ? FLT_MAX : fmaf(ss, djsq, 1e-10f);
        g_D[((uint32_t)(b * KK + i) << 9) + (uint32_t)j] = D;
        sD[r][j] = D;
    }
    __syncthreads();

    // Phase B: warp w min-reduces row w (strided LDS + warp shuffle tree).
    {
        float v = FLT_MAX;
#pragma unroll
        for (int k = 0; k < KK / 32; k++)
            v = fminf(v, sD[wid][lane + 32 * k]);
#pragma unroll
        for (int o = 16; o; o >>= 1)
            v = fminf(v, __shfl_xor_sync(0xffffffffu, v, o));
        if (lane == 0) g_a[b * KK + i0 + wid] = 0.99f * v;
    }
}

// ---------------------------------------------------------------------------
// Kernel 2 (PDL secondary): PRNG phase FIRST (independent of dist), then
// grid-dependency sync, then the D-dependent decisions.
// t[b] = log2(u1)/log2(u0) = L1/L0; decide a^2*t >= bb^2  (R11-validated).
// ---------------------------------------------------------------------------
__global__ void __launch_bounds__(256, 6)
sample_kernel(float* __restrict__ out, uint32_t one) {
    const uint32_t m0 = blockIdx.x * 256u + threadIdx.x;   // (i<<9) + j
    const int i = (int)(m0 >> 9);
    const int j = (int)(m0 & 511u);
    const bool diag = (i == j);

    // Phase 1: pure PRNG — overlaps with the still-running dist kernel.
    float t[BK];
#pragma unroll
    for (int b = 0; b < BK; b++) {
        uint32_t e = 2u * (((uint32_t)b << 18) + m0);
        float u0 = jax_uniform(jax_bits(e,      one));
        float u1 = jax_uniform(jax_bits(e + 1u, one));
        // L = -log2(u) > 0; ratio sign cancels.
        t[b] = __fdividef(__log2f(u1), __log2f(u0));
    }

    // Wait until dist has fully completed (and its writes are visible).
    cudaGridDependencySynchronize();

    // Phase 2: decisions.
    const float* __restrict__ Dp = g_D + m0;
    const float* __restrict__ ap = g_a + i;
    float count = 0.0f;
#pragma unroll
    for (int b = 0; b < BK; b++) {
        float D  = Dp[(uint32_t)b << 18];
        float ar = ap[b << 9];
        float a  = diag ? 0.99f : ar;
        float bb = diag ? 0.01f : D - ar;
        count += (a * a * t[b] >= bb * bb) ? 0.125f : 0.0f;
    }
    out[m0] = count;
}

// ---------------------------------------------------------------------------
// Launch: dist normally; sample as a PDL secondary so its PRNG phase
// overlaps dist's execution.
// ---------------------------------------------------------------------------
extern "C" void kernel_launch(void* const* d_in, const int* in_sizes, int n_in,
                              void* d_out, int out_size) {
    const float* amp = (const float*)d_in[0];
    const float* ph  = (const float*)d_in[1];
    const float* A   = (const float*)d_in[2];
    const float* wa  = (const float*)d_in[3];
    const float* wp  = (const float*)d_in[4];
    float* out = (float*)d_out;

    dist_kernel<<<dim3(KK / ROWS, BK), TPB>>>(amp, ph, A, wa, wp);

    cudaLaunchConfig_t cfg = {};
    cfg.gridDim  = dim3((KK * KK) / 256, 1, 1);
    cfg.blockDim = dim3(256, 1, 1);
    cudaLaunchAttribute attrs[1];
    attrs[0].id = cudaLaunchAttributeProgrammaticStreamSerialization;
    attrs[0].val.programmaticStreamSerializationAllowed = 1;
    cfg.attrs = attrs;
    cfg.numAttrs = 1;
    cudaLaunchKernelEx(&cfg, sample_kernel, out, 1u);
}

// round 17
// speedup vs baseline: 1.4640x; 1.4640x over previous
#include <cuda_runtime.h>
#include <cstdint>
#include <math.h>
#include <float.h>

// Problem constants
#define BK  8
#define CK  32
#define KK  512
#define ROWS 16
#define TPB 512

// Scratch: raw D per (b,i,j); a = 0.99*Dmin per (b,i)
__device__ float g_D[BK * KK * KK];    // 8 MB
__device__ float g_a[BK * KK];         // 16 KB

// ---------------------------------------------------------------------------
// JAX threefry2x32, key = (0, 42).  Random123 Threefry-2x32-20.
// Adds (round + key injection) issued as IMAD via opaque `one` (fma pipe);
// rotations single SHF via __funnelshift_l; xors LOP3. 3 ops per round.
// ---------------------------------------------------------------------------
#define MAD(dst, addend) \
    asm("mad.lo.s32 %0, %1, %2, %0;" : "+r"(dst) : "r"(addend), "r"(one))
#define MADC(dst, cst) { uint32_t k_ = (cst); MAD(dst, k_); }
#define TF_R(r) { MAD(x0, x1); x1 = __funnelshift_l(x1, x1, (r)); x1 ^= x0; }

__device__ __forceinline__ uint32_t jax_bits(uint32_t e, uint32_t one) {
    uint32_t x0 = 0u, x1 = e;
    const uint32_t ks1 = 42u;
    const uint32_t ks2 = 0x1BD11BDAu ^ 42u;
    /* x0 += 0 */  MADC(x1, ks1);
    TF_R(13) TF_R(15) TF_R(26) TF_R(6)
    MADC(x0, ks1); MADC(x1, ks2 + 1u);
    TF_R(17) TF_R(29) TF_R(16) TF_R(24)
    MADC(x0, ks2); MADC(x1, 2u);
    TF_R(13) TF_R(15) TF_R(26) TF_R(6)
    /* x0 += 0 */  MADC(x1, ks1 + 3u);
    TF_R(17) TF_R(29) TF_R(16) TF_R(24)
    MADC(x0, ks1); MADC(x1, ks2 + 4u);
    TF_R(13) TF_R(15) TF_R(26) TF_R(6)
    MADC(x0, ks2); MADC(x1, 5u);
    return x0 ^ x1;
}

// jax.random.uniform bit->float, minval=1e-10, maxval=1.0 (f32).
// f in [0,1) so max(1e-10, f+1e-10) == f+1e-10 exactly.
__device__ __forceinline__ float jax_uniform(uint32_t bits) {
    float f = __uint_as_float((bits >> 9) | 0x3f800000u) - 1.0f;
    return f + 1e-10f;
}

// ---------------------------------------------------------------------------
// Kernel 1: distances + row minima  ->  g_D (raw), g_a (0.99*Dmin)
// 256 blocks (single wave at 2 CTA/SM), 16 rows per block, in-loop warp min.
// (Exact R4 structure — best measured.)
// ---------------------------------------------------------------------------
__global__ void __launch_bounds__(TPB, 2)
dist_kernel(const float* __restrict__ amp,
            const float* __restrict__ ph,
            const float* __restrict__ Amat,
            const float* __restrict__ wamp_p,
            const float* __restrict__ wph_p) {
    __shared__ float sQi[ROWS][CK];      // row vectors q_i
    __shared__ float sSi[ROWS];          // ||q_i||^2
    __shared__ float sRed[16][ROWS];     // per-warp row minima

    const int b    = blockIdx.y;
    const int j    = threadIdx.x;
    const int wid  = j >> 5;
    const int lane = j & 31;
    const int i0   = blockIdx.x * ROWS;

    const float wa = wamp_p[0];
    const float wp = wph_p[0];

    const float* ab = amp + (size_t)b * CK * KK;
    const float* pb = ph  + (size_t)b * CK * KK;

    // Per-thread column cache q_j[c] and its sum of squares
    float qj[CK];
    float Sj = 0.0f;
#pragma unroll
    for (int c = 0; c < CK; c++) {
        float v = wa * ab[c * KK + j] + wp * pb[c * KK + j];
        qj[c] = v;
        Sj = fmaf(v, v, Sj);
    }

    // Each of the 16 warps loads its row vector (lane = channel) + row SSQ
    {
        const int i = i0 + wid;
        float v = wa * ab[lane * KK + i] + wp * pb[lane * KK + i];
        sQi[wid][lane] = v;
        float s = v * v;
#pragma unroll
        for (int o = 16; o; o >>= 1)
            s += __shfl_xor_sync(0xffffffffu, s, o);
        if (lane == 0) sSi[wid] = s;
    }

    const float dj   = Amat[(size_t)j * KK + j];
    const float djsq = dj * dj;
    __syncthreads();

    // Phase A: D = djsq * ||q_i - q_j||^2 + 1e-10 (expanded dot); store raw D,
    // keep per-warp row minimum.
#pragma unroll
    for (int r = 0; r < ROWS; r++) {
        float dot = 0.0f;
        const float2* q2 = (const float2*)sQi[r];
#pragma unroll
        for (int c2 = 0; c2 < CK / 2; c2++) {
            float2 qi = q2[c2];
            dot = fmaf(qi.x, qj[2 * c2], dot);
            dot = fmaf(qi.y, qj[2 * c2 + 1], dot);
        }
        float ss = fmaxf(fmaf(dot, -2.0f, sSi[r] + Sj), 0.0f);
        const int i = i0 + r;
        float D = (i == j) ? FLT_MAX : fmaf(ss, djsq, 1e-10f);
        g_D[((uint32_t)(b * KK + i) << 9) + (uint32_t)j] = D;

        float v = D;
#pragma unroll
        for (int o = 16; o; o >>= 1)
            v = fminf(v, __shfl_xor_sync(0xffffffffu, v, o));
        if (lane == 0) sRed[wid][r] = v;
    }
    __syncthreads();

    // Phase B: combine 16 warp-partials per row; warp w handles row w.
    {
        float v = (lane < 16) ? sRed[lane][wid] : FLT_MAX;
#pragma unroll
        for (int o = 8; o; o >>= 1)
            v = fminf(v, __shfl_xor_sync(0xffffffffu, v, o));
        if (lane == 0) g_a[b * KK + i0 + wid] = 0.99f * v;
    }
}

// ---------------------------------------------------------------------------
// Kernel 2: gumbel-bernoulli decisions + mean over b  ->  out
// One thread per (i,j); small blocks stream to minimize the tail.
// (Exact R4 structure; __log2f since the log base cancels in the compare.)
// ---------------------------------------------------------------------------
__global__ void __launch_bounds__(128, 12)
sample_kernel(float* __restrict__ out, uint32_t one) {
    const uint32_t m0 = blockIdx.x * 128u + threadIdx.x;   // (i<<9) + j
    const int i = (int)(m0 >> 9);
    const int j = (int)(m0 & 511u);
    const bool diag = (i == j);

    const float* __restrict__ Dp = g_D + m0;
    const float* __restrict__ ap = g_a + i;

    float count = 0.0f;
#pragma unroll
    for (int b = 0; b < BK; b++) {
        float D  = Dp[(uint32_t)b << 18];
        float ar = ap[b << 9];
        float a  = diag ? 0.99f : ar;
        float bb = diag ? 0.01f : D - ar;

        uint32_t e = 2u * (((uint32_t)b << 18) + m0);
        float u0 = jax_uniform(jax_bits(e,      one));
        float u1 = jax_uniform(jax_bits(e + 1u, one));
        float L0 = -__log2f(u0);     // positive; log base cancels below
        float L1 = -__log2f(u1);

        count += (a * a * L1 >= bb * bb * L0) ? 0.125f : 0.0f;
    }
    out[m0] = count;
}

// ---------------------------------------------------------------------------
// Launch
// ---------------------------------------------------------------------------
extern "C" void kernel_launch(void* const* d_in, const int* in_sizes, int n_in,
                              void* d_out, int out_size) {
    const float* amp = (const float*)d_in[0];
    const float* ph  = (const float*)d_in[1];
    const float* A   = (const float*)d_in[2];
    const float* wa  = (const float*)d_in[3];
    const float* wp  = (const float*)d_in[4];
    float* out = (float*)d_out;

    dist_kernel<<<dim3(KK / ROWS, BK), TPB>>>(amp, ph, A, wa, wp);
    sample_kernel<<<(KK * KK) / 128, 128>>>(out, 1u);
}